// round 1
// baseline (speedup 1.0000x reference)
#include <cuda_runtime.h>
#include <math.h>

#define MAXB 16384
#define DT 0.01f
#define FULLMASK 0xffffffffu
#define TRI(i,j) ((i)*((i)+1)/2+(j))
#define EPB 4
#define SM_STRIDE 2000

__constant__ float c_LOWER[6] = {-6.28f,-6.28f,-3.14f,-6.28f,-6.28f,-6.28f};
__constant__ float c_UPPER[6] = { 6.28f, 6.28f, 3.14f, 6.28f, 6.28f, 6.28f};
__constant__ float c_EFFORT[6]= {150.f,150.f,150.f,28.f,28.f,28.f};

// stage scratch
__device__ float g_qs [4][MAXB*6];
__device__ float g_qds[4][MAXB*6];
__device__ float g_kqd[4][MAXB*6];
__device__ int   g_viol[4];

__device__ __forceinline__ float sp_f(float x){ return fmaxf(x,0.f)+log1pf(expf(-fabsf(x))); }
__device__ __forceinline__ float sg_f(float x){ return 1.f/(1.f+expf(-x)); }

__global__ void zero_viol_kernel(){ if (threadIdx.x<4) g_viol[threadIdx.x]=0; }

__global__ void prep_kernel(int S, const float* __restrict__ obs, int B){
  int idx=blockIdx.x*blockDim.x+threadIdx.x;
  if (idx>=B*6) return;
  int i=idx/6, j=idx-i*6;
  float q0=obs[i*12+j], qd0=obs[i*12+6+j];
  float qs,qds;
  if      (S==0){ qs=q0;                         qds=qd0; }
  else if (S==1){ qs=q0+0.5f*DT*qd0;             qds=qd0+0.5f*DT*g_kqd[0][idx]; }
  else if (S==2){ qs=q0+0.5f*DT*g_qds[1][idx];   qds=qd0+0.5f*DT*g_kqd[1][idx]; }
  else          { qs=q0+DT*g_qds[2][idx];        qds=qd0+DT*g_kqd[2][idx]; }
  g_qs[S][idx]=qs; g_qds[S][idx]=qds;
  float lo=c_LOWER[j]+0.1f, up=c_UPPER[j]-0.1f;
  if (qs<=lo || qs>=up) atomicOr(&g_viol[S], 1<<j);
}

__global__ void __launch_bounds__(EPB*32)
accel_kernel(int S, const float* __restrict__ action,
    const float* __restrict__ W1L, const float* __restrict__ b1L,
    const float* __restrict__ W2L, const float* __restrict__ b2L,
    const float* __restrict__ W3L, const float* __restrict__ b3L,
    const float* __restrict__ W1V, const float* __restrict__ b1V,
    const float* __restrict__ W2V, const float* __restrict__ b2V,
    const float* __restrict__ W3V, const float* __restrict__ b3V,
    int B)
{
  __shared__ __align__(16) float smem[EPB*SM_STRIDE];
  const int warp=threadIdx.x>>5, lane=threadIdx.x&31;
  const int e=blockIdx.x*EPB+warp;
  if (e>=B) return;
  float* SA=smem+warp*SM_STRIDE;   // 7x128 acts (level-1), reused by V-net
  float* SB=SA+896;                // 7x128 acts (level-2)
  float* SY=SB+896;                // 7x24  (y + 6 tangents dy)
  float* SD=SY+168;                // 21: D = sum_p qd_p dL_p
  float* SG=SD+24;                 // 12: dV/dt

  float q[6],qd[6],cs6[6],sn6[6],t[12];
#pragma unroll
  for (int j=0;j<6;j++){
    q[j]=g_qs[S][e*6+j];
    qd[j]=g_qds[S][e*6+j];
    cs6[j]=cosf(q[j]); sn6[j]=sinf(q[j]);
    t[2*j]=cs6[j]; t[2*j+1]=sn6[j];
  }
  const int vm=g_viol[S];

  // ================= L-net layer 1 (12 -> 128), forward + 6 tangents ============
#pragma unroll
  for (int r=0;r<4;r++){
    int o=r*32+lane;
    const float4* wp=(const float4*)(W1L+o*12);
    float4 wa=__ldg(wp), wb=__ldg(wp+1), wc=__ldg(wp+2);
    float wv[12]={wa.x,wa.y,wa.z,wa.w,wb.x,wb.y,wb.z,wb.w,wc.x,wc.y,wc.z,wc.w};
    float z=__ldg(b1L+o);
#pragma unroll
    for (int i2=0;i2<12;i2++) z+=wv[i2]*t[i2];
    float sg=sg_f(z);
    SA[o]=sp_f(z);
#pragma unroll
    for (int p=0;p<6;p++) SA[(1+p)*128+o]=sg*(wv[2*p+1]*cs6[p]-wv[2*p]*sn6[p]);
  }
  __syncwarp();

  // ================= L-net layer 2 (128 -> 128), 7 vectors ======================
  {
    float acc[4][7];
#pragma unroll
    for(int r=0;r<4;r++)
#pragma unroll
      for(int v=0;v<7;v++) acc[r][v]=0.f;
#pragma unroll 2
    for (int kk=0;kk<128;kk+=4){
      float4 hv[7];
#pragma unroll
      for(int v=0;v<7;v++) hv[v]=*(const float4*)(SA+v*128+kk);
#pragma unroll
      for(int r=0;r<4;r++){
        float4 w=__ldg((const float4*)(W2L+(r*32+lane)*128+kk));
#pragma unroll
        for(int v=0;v<7;v++)
          acc[r][v]+=w.x*hv[v].x+w.y*hv[v].y+w.z*hv[v].z+w.w*hv[v].w;
      }
    }
#pragma unroll
    for(int r=0;r<4;r++){
      int o=r*32+lane;
      float z=acc[r][0]+__ldg(b2L+o);
      float sg=sg_f(z);
      SB[o]=sp_f(z);
#pragma unroll
      for(int p=0;p<6;p++) SB[(1+p)*128+o]=sg*acc[r][1+p];
    }
  }
  __syncwarp();

  // ================= L-net layer 3 (128 -> 21), 7 vectors =======================
  if (lane<21){
    float acc[7]={0.f,0.f,0.f,0.f,0.f,0.f,0.f};
#pragma unroll 2
    for (int kk=0;kk<128;kk+=4){
      float4 w=__ldg((const float4*)(W3L+lane*128+kk));
#pragma unroll
      for(int v=0;v<7;v++){
        float4 hv=*(const float4*)(SB+v*128+kk);
        acc[v]+=w.x*hv.x+w.y*hv.y+w.z*hv.z+w.w*hv.w;
      }
    }
    float z=acc[0]+__ldg(b3L+lane);
    float sg=sg_f(z);
    SY[lane]=sp_f(z);
#pragma unroll
    for(int p=0;p<6;p++) SY[(1+p)*24+lane]=sg*acc[1+p];
  }
  __syncwarp();

  // ================= V-net layer 1 forward (h1v, s1v) ===========================
#pragma unroll
  for (int r=0;r<4;r++){
    int o=r*32+lane;
    const float4* wp=(const float4*)(W1V+o*12);
    float4 wa=__ldg(wp), wb=__ldg(wp+1), wc=__ldg(wp+2);
    float wv[12]={wa.x,wa.y,wa.z,wa.w,wb.x,wb.y,wb.z,wb.w,wc.x,wc.y,wc.z,wc.w};
    float z=__ldg(b1V+o);
#pragma unroll
    for (int i2=0;i2<12;i2++) z+=wv[i2]*t[i2];
    SA[o]=sp_f(z);       // h1v
    SA[128+o]=sg_f(z);   // s1v
  }
  __syncwarp();

  // ================= V-net layer 2 forward + r2 = W3V .* sigmoid(z2) ============
  {
    float acc[4]={0.f,0.f,0.f,0.f};
#pragma unroll 2
    for(int kk=0;kk<128;kk+=4){
      float4 hv=*(const float4*)(SA+kk);
#pragma unroll
      for(int r=0;r<4;r++){
        float4 w=__ldg((const float4*)(W2V+(r*32+lane)*128+kk));
        acc[r]+=w.x*hv.x+w.y*hv.y+w.z*hv.z+w.w*hv.w;
      }
    }
#pragma unroll
    for(int r=0;r<4;r++){
      int o=r*32+lane;
      float z=acc[r]+__ldg(b2V+o);
      SA[256+o]=__ldg(W3V+o)*sg_f(z);   // r2 = dV/dz2
    }
  }
  __syncwarp();

  // ================= V-net backward: dV/dt (12 values) ==========================
  float gpart[12];
  {
    float ax=0.f,ay=0.f,az=0.f,aw=0.f;
#pragma unroll 4
    for(int j2=0;j2<128;j2++){
      float rj=SA[256+j2];
      float4 w=__ldg((const float4*)(W2V+j2*128+4*lane));
      ax+=rj*w.x; ay+=rj*w.y; az+=rj*w.z; aw+=rj*w.w;
    }
    float4 s1v=*(const float4*)(SA+128+4*lane);
    float r1v[4]={ax*s1v.x, ay*s1v.y, az*s1v.z, aw*s1v.w};  // dV/dz1
#pragma unroll
    for(int m=0;m<12;m++) gpart[m]=0.f;
#pragma unroll
    for(int tt=0;tt<4;tt++){
      const float4* wp=(const float4*)(W1V+(4*lane+tt)*12);
      float4 wa=__ldg(wp), wb=__ldg(wp+1), wc=__ldg(wp+2);
      float wv[12]={wa.x,wa.y,wa.z,wa.w,wb.x,wb.y,wb.z,wb.w,wc.x,wc.y,wc.z,wc.w};
#pragma unroll
      for(int m=0;m<12;m++) gpart[m]+=r1v[tt]*wv[m];
    }
#pragma unroll
    for(int off=16;off>=1;off>>=1)
#pragma unroll
      for(int m=0;m<12;m++) gpart[m]+=__shfl_xor_sync(FULLMASK,gpart[m],off);
    if (lane==0){
#pragma unroll
      for(int m=0;m<12;m++) SG[m]=gpart[m];
    }
  }
  __syncwarp();

  // ================= assembly: Coriolis, gravity, constraints, solve ============
  // D[m] = sum_p qd[p]*dL_p[m]
  if (lane<21){
    float Dm=0.f;
#pragma unroll
    for(int p=0;p<6;p++) Dm+=qd[p]*SY[(1+p)*24+lane];
    SD[lane]=Dm;
  }
  __syncwarp();

  const int li = (lane<6)?lane:5;
  float w6[6],u6[6],Dq[6];
#pragma unroll
  for(int k=0;k<6;k++){
    float sw=0.f,su=0.f,sd=0.f;
#pragma unroll
    for(int i2=0;i2<6;i2++){
      if (i2>=k){
        int m=TRI(i2,k);
        float a=qd[i2];
        sw+=SY[m]*a;
        su+=SY[(1+li)*24+m]*a;
        sd+=SD[m]*a;
      }
    }
    w6[k]=sw; u6[k]=su; Dq[k]=sd;
  }
  float term2=0.f;
#pragma unroll
  for(int k=0;k<6;k++) term2+=w6[k]*u6[k];
  const int base=li*(li+1)/2;
  float Dw=0.f, LDq=0.f;
#pragma unroll
  for(int j2=0;j2<6;j2++) if (j2<=li){ Dw+=SD[base+j2]*w6[j2]; LDq+=SY[base+j2]*Dq[j2]; }
  float ci=Dw+LDq-term2;

  float qsi = li==0?q[0]:li==1?q[1]:li==2?q[2]:li==3?q[3]:li==4?q[4]:q[5];
  float sni = li==0?sn6[0]:li==1?sn6[1]:li==2?sn6[2]:li==3?sn6[3]:li==4?sn6[4]:sn6[5];
  float csi = li==0?cs6[0]:li==1?cs6[1]:li==2?cs6[2]:li==3?cs6[3]:li==4?cs6[4]:cs6[5];
  float gi = -SG[2*li]*sni + SG[2*li+1]*csi;

  float lo=c_LOWER[li]+0.1f, up=c_UPPER[li]-0.1f;
  float fi;
  if ((vm>>li)&1) fi = (qsi<=lo)?c_EFFORT[li]:((qsi>=up)?-c_EFFORT[li]:0.f);
  else            fi = -5.f*(1.f/(qsi-lo)-1.f/(up-qsi));
  float tau=__ldg(action+e*6+li)*c_EFFORT[li];
  float rhs=tau-ci-gi-fi;

  // solve (L L^T) x = rhs with L from SY (softplus => positive diagonal)
  float accf=rhs, yvv=0.f;
#pragma unroll
  for(int j2=0;j2<6;j2++){
    float yj=__shfl_sync(FULLMASK,accf,j2)/SY[TRI(j2,j2)];
    if (lane==j2) yvv=yj;
    if (lane>j2 && lane<6) accf-=SY[base+j2]*yj;
  }
  float acc2=yvv, xi=0.f;
#pragma unroll
  for(int j2=5;j2>=0;j2--){
    float xj=__shfl_sync(FULLMASK,acc2,j2)/SY[TRI(j2,j2)];
    if (lane==j2) xi=xj;
    if (lane<j2) acc2-=SY[TRI(j2,lane)]*xj;
  }
  if (lane<6) g_kqd[S][e*6+lane]=xi;
}

__global__ void final_kernel(const float* __restrict__ obs, float* __restrict__ out, int B){
  int idx=blockIdx.x*blockDim.x+threadIdx.x;
  if (idx>=B*6) return;
  int i=idx/6, j=idx-i*6;
  float q0=obs[i*12+j], qd0=obs[i*12+6+j];
  const float c1=DT/6.f;
  float qn=q0+c1*(g_qds[0][idx]+2.f*g_qds[1][idx]+2.f*g_qds[2][idx]+g_qds[3][idx]);
  qn=fminf(fmaxf(qn,c_LOWER[j]),c_UPPER[j]);
  float qdn=qd0+c1*(g_kqd[0][idx]+2.f*g_kqd[1][idx]+2.f*g_kqd[2][idx]+g_kqd[3][idx]);
  out[i*12+j]=qn;
  out[i*12+6+j]=qdn;
}

extern "C" void kernel_launch(void* const* d_in, const int* in_sizes, int n_in,
                              void* d_out, int out_size)
{
  const float* obs   =(const float*)d_in[0];
  const float* action=(const float*)d_in[1];
  const float* W1L=(const float*)d_in[2];  const float* b1L=(const float*)d_in[3];
  const float* W2L=(const float*)d_in[4];  const float* b2L=(const float*)d_in[5];
  const float* W3L=(const float*)d_in[6];  const float* b3L=(const float*)d_in[7];
  const float* W1V=(const float*)d_in[8];  const float* b1V=(const float*)d_in[9];
  const float* W2V=(const float*)d_in[10]; const float* b2V=(const float*)d_in[11];
  const float* W3V=(const float*)d_in[12]; const float* b3V=(const float*)d_in[13];
  float* out=(float*)d_out;
  int B=in_sizes[0]/12;
  if (B>MAXB) B=MAXB;

  int nbE=(B*6+127)/128;
  int nbA=(B+EPB-1)/EPB;

  zero_viol_kernel<<<1,32>>>();
  for (int s=0;s<4;s++){
    prep_kernel<<<nbE,128>>>(s,obs,B);
    accel_kernel<<<nbA,EPB*32>>>(s,action,
        W1L,b1L,W2L,b2L,W3L,b3L,
        W1V,b1V,W2V,b2V,W3V,b3V,B);
  }
  final_kernel<<<nbE,128>>>(obs,out,B);
}

// round 2
// speedup vs baseline: 1.0004x; 1.0004x over previous
#include <cuda_runtime.h>
#include <math.h>

#define MAXB 16384
#define DT 0.01f
#define FULLMASK 0xffffffffu
#define TRI(i,j) ((i)*((i)+1)/2+(j))
#define EPB 4
#define SM_STRIDE 2000

__constant__ float c_LOWER[6] = {-6.28f,-6.28f,-3.14f,-6.28f,-6.28f,-6.28f};
__constant__ float c_UPPER[6] = { 6.28f, 6.28f, 3.14f, 6.28f, 6.28f, 6.28f};
__constant__ float c_EFFORT[6]= {150.f,150.f,150.f,28.f,28.f,28.f};

// stage scratch
__device__ float g_qs [4][MAXB*6];
__device__ float g_qds[4][MAXB*6];
__device__ float g_kqd[4][MAXB*6];
__device__ int   g_viol[4];

__device__ __forceinline__ float sp_f(float x){ return fmaxf(x,0.f)+log1pf(expf(-fabsf(x))); }
__device__ __forceinline__ float sg_f(float x){ return 1.f/(1.f+expf(-x)); }

__global__ void zero_viol_kernel(){ if (threadIdx.x<4) g_viol[threadIdx.x]=0; }

__global__ void prep_kernel(int S, const float* __restrict__ obs, int B){
  int idx=blockIdx.x*blockDim.x+threadIdx.x;
  if (idx>=B*6) return;
  int i=idx/6, j=idx-i*6;
  float q0=obs[i*12+j], qd0=obs[i*12+6+j];
  float qs,qds;
  if      (S==0){ qs=q0;                         qds=qd0; }
  else if (S==1){ qs=q0+0.5f*DT*qd0;             qds=qd0+0.5f*DT*g_kqd[0][idx]; }
  else if (S==2){ qs=q0+0.5f*DT*g_qds[1][idx];   qds=qd0+0.5f*DT*g_kqd[1][idx]; }
  else          { qs=q0+DT*g_qds[2][idx];        qds=qd0+DT*g_kqd[2][idx]; }
  g_qs[S][idx]=qs; g_qds[S][idx]=qds;
  float lo=c_LOWER[j]+0.1f, up=c_UPPER[j]-0.1f;
  if (qs<=lo || qs>=up) atomicOr(&g_viol[S], 1<<j);
}

__global__ void __launch_bounds__(EPB*32)
accel_kernel(int S, const float* __restrict__ action,
    const float* __restrict__ W1L, const float* __restrict__ b1L,
    const float* __restrict__ W2L, const float* __restrict__ b2L,
    const float* __restrict__ W3L, const float* __restrict__ b3L,
    const float* __restrict__ W1V, const float* __restrict__ b1V,
    const float* __restrict__ W2V, const float* __restrict__ b2V,
    const float* __restrict__ W3V, const float* __restrict__ b3V,
    int B)
{
  __shared__ __align__(16) float smem[EPB*SM_STRIDE];
  const int warp=threadIdx.x>>5, lane=threadIdx.x&31;
  const int e=blockIdx.x*EPB+warp;
  if (e>=B) return;
  float* SA=smem+warp*SM_STRIDE;   // 7x128 acts (level-1), reused by V-net
  float* SB=SA+896;                // 7x128 acts (level-2)
  float* SY=SB+896;                // 7x24  (y + 6 tangents dy)
  float* SD=SY+168;                // 21: D = sum_p qd_p dL_p
  float* SG=SD+24;                 // 12: dV/dt

  float q[6],qd[6],cs6[6],sn6[6],t[12];
#pragma unroll
  for (int j=0;j<6;j++){
    q[j]=g_qs[S][e*6+j];
    qd[j]=g_qds[S][e*6+j];
    cs6[j]=cosf(q[j]); sn6[j]=sinf(q[j]);
    t[2*j]=cs6[j]; t[2*j+1]=sn6[j];
  }
  const int vm=g_viol[S];

  // ================= L-net layer 1 (12 -> 128), forward + 6 tangents ============
#pragma unroll
  for (int r=0;r<4;r++){
    int o=r*32+lane;
    const float4* wp=(const float4*)(W1L+o*12);
    float4 wa=__ldg(wp), wb=__ldg(wp+1), wc=__ldg(wp+2);
    float wv[12]={wa.x,wa.y,wa.z,wa.w,wb.x,wb.y,wb.z,wb.w,wc.x,wc.y,wc.z,wc.w};
    float z=__ldg(b1L+o);
#pragma unroll
    for (int i2=0;i2<12;i2++) z+=wv[i2]*t[i2];
    float sg=sg_f(z);
    SA[o]=sp_f(z);
#pragma unroll
    for (int p=0;p<6;p++) SA[(1+p)*128+o]=sg*(wv[2*p+1]*cs6[p]-wv[2*p]*sn6[p]);
  }
  __syncwarp();

  // ================= L-net layer 2 (128 -> 128), 7 vectors ======================
  {
    float acc[4][7];
#pragma unroll
    for(int r=0;r<4;r++)
#pragma unroll
      for(int v=0;v<7;v++) acc[r][v]=0.f;
#pragma unroll 2
    for (int kk=0;kk<128;kk+=4){
      float4 hv[7];
#pragma unroll
      for(int v=0;v<7;v++) hv[v]=*(const float4*)(SA+v*128+kk);
#pragma unroll
      for(int r=0;r<4;r++){
        float4 w=__ldg((const float4*)(W2L+(r*32+lane)*128+kk));
#pragma unroll
        for(int v=0;v<7;v++)
          acc[r][v]+=w.x*hv[v].x+w.y*hv[v].y+w.z*hv[v].z+w.w*hv[v].w;
      }
    }
#pragma unroll
    for(int r=0;r<4;r++){
      int o=r*32+lane;
      float z=acc[r][0]+__ldg(b2L+o);
      float sg=sg_f(z);
      SB[o]=sp_f(z);
#pragma unroll
      for(int p=0;p<6;p++) SB[(1+p)*128+o]=sg*acc[r][1+p];
    }
  }
  __syncwarp();

  // ================= L-net layer 3 (128 -> 21), 7 vectors =======================
  if (lane<21){
    float acc[7]={0.f,0.f,0.f,0.f,0.f,0.f,0.f};
#pragma unroll 2
    for (int kk=0;kk<128;kk+=4){
      float4 w=__ldg((const float4*)(W3L+lane*128+kk));
#pragma unroll
      for(int v=0;v<7;v++){
        float4 hv=*(const float4*)(SB+v*128+kk);
        acc[v]+=w.x*hv.x+w.y*hv.y+w.z*hv.z+w.w*hv.w;
      }
    }
    float z=acc[0]+__ldg(b3L+lane);
    float sg=sg_f(z);
    SY[lane]=sp_f(z);
#pragma unroll
    for(int p=0;p<6;p++) SY[(1+p)*24+lane]=sg*acc[1+p];
  }
  __syncwarp();

  // ================= V-net layer 1 forward (h1v, s1v) ===========================
#pragma unroll
  for (int r=0;r<4;r++){
    int o=r*32+lane;
    const float4* wp=(const float4*)(W1V+o*12);
    float4 wa=__ldg(wp), wb=__ldg(wp+1), wc=__ldg(wp+2);
    float wv[12]={wa.x,wa.y,wa.z,wa.w,wb.x,wb.y,wb.z,wb.w,wc.x,wc.y,wc.z,wc.w};
    float z=__ldg(b1V+o);
#pragma unroll
    for (int i2=0;i2<12;i2++) z+=wv[i2]*t[i2];
    SA[o]=sp_f(z);       // h1v
    SA[128+o]=sg_f(z);   // s1v
  }
  __syncwarp();

  // ================= V-net layer 2 forward + r2 = W3V .* sigmoid(z2) ============
  {
    float acc[4]={0.f,0.f,0.f,0.f};
#pragma unroll 2
    for(int kk=0;kk<128;kk+=4){
      float4 hv=*(const float4*)(SA+kk);
#pragma unroll
      for(int r=0;r<4;r++){
        float4 w=__ldg((const float4*)(W2V+(r*32+lane)*128+kk));
        acc[r]+=w.x*hv.x+w.y*hv.y+w.z*hv.z+w.w*hv.w;
      }
    }
#pragma unroll
    for(int r=0;r<4;r++){
      int o=r*32+lane;
      float z=acc[r]+__ldg(b2V+o);
      SA[256+o]=__ldg(W3V+o)*sg_f(z);   // r2 = dV/dz2
    }
  }
  __syncwarp();

  // ================= V-net backward: dV/dt (12 values) ==========================
  float gpart[12];
  {
    float ax=0.f,ay=0.f,az=0.f,aw=0.f;
#pragma unroll 4
    for(int j2=0;j2<128;j2++){
      float rj=SA[256+j2];
      float4 w=__ldg((const float4*)(W2V+j2*128+4*lane));
      ax+=rj*w.x; ay+=rj*w.y; az+=rj*w.z; aw+=rj*w.w;
    }
    float4 s1v=*(const float4*)(SA+128+4*lane);
    float r1v[4]={ax*s1v.x, ay*s1v.y, az*s1v.z, aw*s1v.w};  // dV/dz1
#pragma unroll
    for(int m=0;m<12;m++) gpart[m]=0.f;
#pragma unroll
    for(int tt=0;tt<4;tt++){
      const float4* wp=(const float4*)(W1V+(4*lane+tt)*12);
      float4 wa=__ldg(wp), wb=__ldg(wp+1), wc=__ldg(wp+2);
      float wv[12]={wa.x,wa.y,wa.z,wa.w,wb.x,wb.y,wb.z,wb.w,wc.x,wc.y,wc.z,wc.w};
#pragma unroll
      for(int m=0;m<12;m++) gpart[m]+=r1v[tt]*wv[m];
    }
#pragma unroll
    for(int off=16;off>=1;off>>=1)
#pragma unroll
      for(int m=0;m<12;m++) gpart[m]+=__shfl_xor_sync(FULLMASK,gpart[m],off);
    if (lane==0){
#pragma unroll
      for(int m=0;m<12;m++) SG[m]=gpart[m];
    }
  }
  __syncwarp();

  // ================= assembly: Coriolis, gravity, constraints, solve ============
  // D[m] = sum_p qd[p]*dL_p[m]
  if (lane<21){
    float Dm=0.f;
#pragma unroll
    for(int p=0;p<6;p++) Dm+=qd[p]*SY[(1+p)*24+lane];
    SD[lane]=Dm;
  }
  __syncwarp();

  const int li = (lane<6)?lane:5;
  float w6[6],u6[6],Dq[6];
#pragma unroll
  for(int k=0;k<6;k++){
    float sw=0.f,su=0.f,sd=0.f;
#pragma unroll
    for(int i2=0;i2<6;i2++){
      if (i2>=k){
        int m=TRI(i2,k);
        float a=qd[i2];
        sw+=SY[m]*a;
        su+=SY[(1+li)*24+m]*a;
        sd+=SD[m]*a;
      }
    }
    w6[k]=sw; u6[k]=su; Dq[k]=sd;
  }
  float term2=0.f;
#pragma unroll
  for(int k=0;k<6;k++) term2+=w6[k]*u6[k];
  const int base=li*(li+1)/2;
  float Dw=0.f, LDq=0.f;
#pragma unroll
  for(int j2=0;j2<6;j2++) if (j2<=li){ Dw+=SD[base+j2]*w6[j2]; LDq+=SY[base+j2]*Dq[j2]; }
  float ci=Dw+LDq-term2;

  float qsi = li==0?q[0]:li==1?q[1]:li==2?q[2]:li==3?q[3]:li==4?q[4]:q[5];
  float sni = li==0?sn6[0]:li==1?sn6[1]:li==2?sn6[2]:li==3?sn6[3]:li==4?sn6[4]:sn6[5];
  float csi = li==0?cs6[0]:li==1?cs6[1]:li==2?cs6[2]:li==3?cs6[3]:li==4?cs6[4]:cs6[5];
  float gi = -SG[2*li]*sni + SG[2*li+1]*csi;

  float lo=c_LOWER[li]+0.1f, up=c_UPPER[li]-0.1f;
  float fi;
  if ((vm>>li)&1) fi = (qsi<=lo)?c_EFFORT[li]:((qsi>=up)?-c_EFFORT[li]:0.f);
  else            fi = -5.f*(1.f/(qsi-lo)-1.f/(up-qsi));
  float tau=__ldg(action+e*6+li)*c_EFFORT[li];
  float rhs=tau-ci-gi-fi;

  // solve (L L^T) x = rhs with L from SY (softplus => positive diagonal)
  float accf=rhs, yvv=0.f;
#pragma unroll
  for(int j2=0;j2<6;j2++){
    float yj=__shfl_sync(FULLMASK,accf,j2)/SY[TRI(j2,j2)];
    if (lane==j2) yvv=yj;
    if (lane>j2 && lane<6) accf-=SY[base+j2]*yj;
  }
  float acc2=yvv, xi=0.f;
#pragma unroll
  for(int j2=5;j2>=0;j2--){
    float xj=__shfl_sync(FULLMASK,acc2,j2)/SY[TRI(j2,j2)];
    if (lane==j2) xi=xj;
    if (lane<j2) acc2-=SY[TRI(j2,lane)]*xj;
  }
  if (lane<6) g_kqd[S][e*6+lane]=xi;
}

__global__ void final_kernel(const float* __restrict__ obs, float* __restrict__ out, int B){
  int idx=blockIdx.x*blockDim.x+threadIdx.x;
  if (idx>=B*6) return;
  int i=idx/6, j=idx-i*6;
  float q0=obs[i*12+j], qd0=obs[i*12+6+j];
  const float c1=DT/6.f;
  float qn=q0+c1*(g_qds[0][idx]+2.f*g_qds[1][idx]+2.f*g_qds[2][idx]+g_qds[3][idx]);
  qn=fminf(fmaxf(qn,c_LOWER[j]),c_UPPER[j]);
  float qdn=qd0+c1*(g_kqd[0][idx]+2.f*g_kqd[1][idx]+2.f*g_kqd[2][idx]+g_kqd[3][idx]);
  out[i*12+j]=qn;
  out[i*12+6+j]=qdn;
}

extern "C" void kernel_launch(void* const* d_in, const int* in_sizes, int n_in,
                              void* d_out, int out_size)
{
  const float* obs   =(const float*)d_in[0];
  const float* action=(const float*)d_in[1];
  const float* W1L=(const float*)d_in[2];  const float* b1L=(const float*)d_in[3];
  const float* W2L=(const float*)d_in[4];  const float* b2L=(const float*)d_in[5];
  const float* W3L=(const float*)d_in[6];  const float* b3L=(const float*)d_in[7];
  const float* W1V=(const float*)d_in[8];  const float* b1V=(const float*)d_in[9];
  const float* W2V=(const float*)d_in[10]; const float* b2V=(const float*)d_in[11];
  const float* W3V=(const float*)d_in[12]; const float* b3V=(const float*)d_in[13];
  float* out=(float*)d_out;
  int B=in_sizes[0]/12;
  if (B>MAXB) B=MAXB;

  int nbE=(B*6+127)/128;
  int nbA=(B+EPB-1)/EPB;

  zero_viol_kernel<<<1,32>>>();
  for (int s=0;s<4;s++){
    prep_kernel<<<nbE,128>>>(s,obs,B);
    accel_kernel<<<nbA,EPB*32>>>(s,action,
        W1L,b1L,W2L,b2L,W3L,b3L,
        W1V,b1V,W2V,b2V,W3V,b3V,B);
  }
  final_kernel<<<nbE,128>>>(obs,out,B);
}

// round 3
// speedup vs baseline: 1.8533x; 1.8525x over previous
#include <cuda_runtime.h>
#include <math.h>

#define MAXB 16384
#define DT 0.01f
#define FULLMASK 0xffffffffu
#define TRI(i,j) ((i)*((i)+1)/2+(j))

__constant__ float c_LOWER[6] = {-6.28f,-6.28f,-3.14f,-6.28f,-6.28f,-6.28f};
__constant__ float c_UPPER[6] = { 6.28f, 6.28f, 3.14f, 6.28f, 6.28f, 6.28f};
__constant__ float c_EFFORT[6]= {150.f,150.f,150.f,28.f,28.f,28.f};

__device__ float g_qs [4][MAXB*6];
__device__ float g_qds[4][MAXB*6];
__device__ float g_kqd[4][MAXB*6];
__device__ int   g_viol[4];

// tf32-prepped weights
__device__ float g_W1L16 [128*16];
__device__ float g_W2Lp  [128*128];
__device__ float g_W3L24 [24*128];
__device__ float g_W1V16 [128*16];
__device__ float g_W2Vp  [128*128];
__device__ float g_W2VT  [128*128];
__device__ float g_W1VT16[16*128];

__device__ __forceinline__ float rna(float x){
  unsigned u; asm("cvt.rna.tf32.f32 %0, %1;":"=r"(u):"f"(x)); return __uint_as_float(u);
}
__device__ __forceinline__ float sp_f(float x){ return fmaxf(x,0.f)+log1pf(__expf(-fabsf(x))); }
__device__ __forceinline__ float sg_f(float x){ return __frcp_rn(1.f+__expf(-x)); }
__device__ __forceinline__ void mma8(float&d0,float&d1,float&d2,float&d3,
    unsigned a0,unsigned a1,unsigned a2,unsigned a3,unsigned b0,unsigned b1){
  asm volatile("mma.sync.aligned.m16n8k8.row.col.f32.tf32.tf32.f32 "
    "{%0,%1,%2,%3},{%4,%5,%6,%7},{%8,%9},{%0,%1,%2,%3};"
    :"+f"(d0),"+f"(d1),"+f"(d2),"+f"(d3)
    :"r"(a0),"r"(a1),"r"(a2),"r"(a3),"r"(b0),"r"(b1));
}
__device__ __forceinline__ int swz(int r,int c){ return (r<<7)+(c^((r&7)<<2)); }
#define F2U __float_as_uint

__global__ void zero_viol_kernel(){ if (threadIdx.x<4) g_viol[threadIdx.x]=0; }

__global__ void prep_weights_kernel(const float* __restrict__ W1L,const float* __restrict__ b1L,
    const float* __restrict__ W2L,const float* __restrict__ W3L,
    const float* __restrict__ W1V,const float* __restrict__ b1V,const float* __restrict__ W2V){
  int i=blockIdx.x*blockDim.x+threadIdx.x;
  if      (i<2048){ int o=i>>4,k=i&15; g_W1L16[i]=rna(k<12?W1L[o*12+k]:(k==12?b1L[o]:0.f)); }
  else if (i<18432){ int j=i-2048; g_W2Lp[j]=rna(W2L[j]); }
  else if (i<21504){ int j=i-18432; int r=j>>7,c=j&127; g_W3L24[j]=rna(r<21?W3L[r*128+c]:0.f); }
  else if (i<23552){ int j=i-21504; int o=j>>4,k=j&15; g_W1V16[j]=rna(k<12?W1V[o*12+k]:(k==12?b1V[o]:0.f)); }
  else if (i<39936){ int j=i-23552; g_W2Vp[j]=rna(W2V[j]); }
  else if (i<56320){ int j=i-39936; int n=j>>7,k2=j&127; g_W2VT[j]=rna(W2V[k2*128+n]); }
  else if (i<58368){ int j=i-56320; int m=j>>7,k2=j&127; g_W1VT16[j]=rna(m<12?W1V[k2*12+m]:0.f); }
}

__global__ void prep_kernel(int S, const float* __restrict__ obs, int B){
  int idx=blockIdx.x*blockDim.x+threadIdx.x;
  if (idx>=B*6) return;
  int i=idx/6, j=idx-i*6;
  float q0=obs[i*12+j], qd0=obs[i*12+6+j];
  float qs,qds;
  if      (S==0){ qs=q0;                       qds=qd0; }
  else if (S==1){ qs=q0+0.5f*DT*qd0;           qds=qd0+0.5f*DT*g_kqd[0][idx]; }
  else if (S==2){ qs=q0+0.5f*DT*g_qds[1][idx]; qds=qd0+0.5f*DT*g_kqd[1][idx]; }
  else          { qs=q0+DT*g_qds[2][idx];      qds=qd0+DT*g_kqd[2][idx]; }
  g_qs[S][idx]=qs; g_qds[S][idx]=qds;
  float lo=c_LOWER[j]+0.1f, up=c_UPPER[j]-0.1f;
  if (qs<=lo || qs>=up) atomicOr(&g_viol[S], 1<<j);
}

// smem layout (floats)
#define S_H    0
#define S_H0   16384
#define S_VIN  18944
#define S_H1V  19264
#define S_R2   21312
#define S_SL   23360
#define S_SG   26560
#define SMEM_FLOATS 26752

__global__ void __launch_bounds__(128)
accel_mma_kernel(int S, const float* __restrict__ action,
    const float* __restrict__ b2L, const float* __restrict__ b3L,
    const float* __restrict__ b2V, const float* __restrict__ W3V, int B)
{
  extern __shared__ float sm[];
  const int tid=threadIdx.x, w=tid>>5, lane=tid&31;
  const int gid=lane>>2, tig=lane&3;
  const int eb=blockIdx.x*16;
  const int vm=g_viol[S];

  // ---------- P0: build A matrices ----------
  {
    int row=tid, ch=row&7, el=row>>3;
    int e=eb+el; if (e>=B) e=B-1;
    float t16[16];
#pragma unroll
    for(int k=0;k<16;k++) t16[k]=0.f;
    if (ch==0){
#pragma unroll
      for(int j=0;j<6;j++){ float qj=g_qs[S][e*6+j]; t16[2*j]=cosf(qj); t16[2*j+1]=sinf(qj); }
      t16[12]=1.f;
    } else if (ch<7){
      int p=ch-1; float qp=g_qs[S][e*6+p];
      t16[2*p]=-sinf(qp); t16[2*p+1]=cosf(qp);
    }
#pragma unroll
    for(int k=0;k<16;k++) sm[S_H0+row*20+k]=rna(t16[k]);
    if (ch==0){
#pragma unroll
      for(int k=0;k<16;k++) sm[S_VIN+el*20+k]=rna(t16[k]);
    }
  }
  __syncthreads();

  // ---------- P1: V layer1 + L layer1 ----------
  {
    float DV[4][4]={};
#pragma unroll
    for(int kt=0;kt<2;kt++){
      int c0=kt*8+tig;
      unsigned a0=F2U(sm[S_VIN+gid*20+c0]),     a1=F2U(sm[S_VIN+(gid+8)*20+c0]);
      unsigned a2=F2U(sm[S_VIN+gid*20+c0+4]),   a3=F2U(sm[S_VIN+(gid+8)*20+c0+4]);
#pragma unroll
      for(int nt=0;nt<4;nt++){
        int n=w*32+nt*8+gid;
        mma8(DV[nt][0],DV[nt][1],DV[nt][2],DV[nt][3],a0,a1,a2,a3,
             F2U(g_W1V16[n*16+kt*8+tig]),F2U(g_W1V16[n*16+kt*8+tig+4]));
      }
    }
#pragma unroll
    for(int nt=0;nt<4;nt++){
      int c0=w*32+nt*8+tig*2;
      *(float2*)&sm[S_H1V+swz(gid,c0)]  =make_float2(rna(sp_f(DV[nt][0])),rna(sp_f(DV[nt][1])));
      *(float2*)&sm[S_H1V+swz(gid+8,c0)]=make_float2(rna(sp_f(DV[nt][2])),rna(sp_f(DV[nt][3])));
    }
    float D[8][4][4]={};
#pragma unroll
    for(int kt=0;kt<2;kt++){
      unsigned Bf[4][2];
#pragma unroll
      for(int nt=0;nt<4;nt++){
        int n=w*32+nt*8+gid;
        Bf[nt][0]=F2U(g_W1L16[n*16+kt*8+tig]); Bf[nt][1]=F2U(g_W1L16[n*16+kt*8+tig+4]);
      }
#pragma unroll
      for(int m=0;m<8;m++){
        int r0=m*16+gid, c0=kt*8+tig;
        unsigned a0=F2U(sm[S_H0+r0*20+c0]),   a1=F2U(sm[S_H0+(r0+8)*20+c0]);
        unsigned a2=F2U(sm[S_H0+r0*20+c0+4]), a3=F2U(sm[S_H0+(r0+8)*20+c0+4]);
#pragma unroll
        for(int nt=0;nt<4;nt++)
          mma8(D[m][nt][0],D[m][nt][1],D[m][nt][2],D[m][nt][3],a0,a1,a2,a3,Bf[nt][0],Bf[nt][1]);
      }
    }
#pragma unroll
    for(int m=0;m<8;m++)
#pragma unroll
      for(int nt=0;nt<4;nt++){
        float d0=D[m][nt][0],d1=D[m][nt][1],d2=D[m][nt][2],d3=D[m][nt][3];
        float z0=__shfl_sync(FULLMASK,d0,tig), z1=__shfl_sync(FULLMASK,d1,tig);
        float z2=__shfl_sync(FULLMASK,d2,tig), z3=__shfl_sync(FULLMASK,d3,tig);
        int c0=w*32+nt*8+tig*2;
        float o0,o1,o2,o3;
        if (gid==0){ o0=sp_f(z0);o1=sp_f(z1);o2=sp_f(z2);o3=sp_f(z3); }
        else if (gid<7){ o0=sg_f(z0)*d0;o1=sg_f(z1)*d1;o2=sg_f(z2)*d2;o3=sg_f(z3)*d3; }
        else { o0=0.f;o1=0.f;o2=0.f;o3=0.f; }
        *(float2*)&sm[S_H+swz(m*16+gid,c0)]  =make_float2(rna(o0),rna(o1));
        *(float2*)&sm[S_H+swz(m*16+8+gid,c0)]=make_float2(rna(o2),rna(o3));
      }
  }
  __syncthreads();

  // ---------- P2: V layer2 + L layer2 (in place) ----------
  {
    float DV[4][4]={};
#pragma unroll 4
    for(int kt=0;kt<16;kt++){
      int c0=kt*8+tig;
      unsigned a0=F2U(sm[S_H1V+swz(gid,c0)]),   a1=F2U(sm[S_H1V+swz(gid+8,c0)]);
      unsigned a2=F2U(sm[S_H1V+swz(gid,c0+4)]), a3=F2U(sm[S_H1V+swz(gid+8,c0+4)]);
#pragma unroll
      for(int nt=0;nt<4;nt++){
        int n=w*32+nt*8+gid;
        mma8(DV[nt][0],DV[nt][1],DV[nt][2],DV[nt][3],a0,a1,a2,a3,
             F2U(g_W2Vp[n*128+kt*8+tig]),F2U(g_W2Vp[n*128+kt*8+tig+4]));
      }
    }
#pragma unroll
    for(int nt=0;nt<4;nt++){
      int c0=w*32+nt*8+tig*2;
      float bv0=__ldg(b2V+c0),bv1=__ldg(b2V+c0+1),w30=__ldg(W3V+c0),w31=__ldg(W3V+c0+1);
      *(float2*)&sm[S_R2+swz(gid,c0)]  =make_float2(rna(w30*sg_f(DV[nt][0]+bv0)),rna(w31*sg_f(DV[nt][1]+bv1)));
      *(float2*)&sm[S_R2+swz(gid+8,c0)]=make_float2(rna(w30*sg_f(DV[nt][2]+bv0)),rna(w31*sg_f(DV[nt][3]+bv1)));
    }
    float D[8][4][4]={};
#pragma unroll 2
    for(int kt=0;kt<16;kt++){
      unsigned Bf[4][2];
#pragma unroll
      for(int nt=0;nt<4;nt++){
        int n=w*32+nt*8+gid;
        Bf[nt][0]=F2U(g_W2Lp[n*128+kt*8+tig]); Bf[nt][1]=F2U(g_W2Lp[n*128+kt*8+tig+4]);
      }
#pragma unroll
      for(int m=0;m<8;m++){
        int r0=m*16+gid, c0=kt*8+tig;
        unsigned a0=F2U(sm[S_H+swz(r0,c0)]),   a1=F2U(sm[S_H+swz(r0+8,c0)]);
        unsigned a2=F2U(sm[S_H+swz(r0,c0+4)]), a3=F2U(sm[S_H+swz(r0+8,c0+4)]);
#pragma unroll
        for(int nt=0;nt<4;nt++)
          mma8(D[m][nt][0],D[m][nt][1],D[m][nt][2],D[m][nt][3],a0,a1,a2,a3,Bf[nt][0],Bf[nt][1]);
      }
    }
    __syncthreads();   // all warps done reading H
    float bL0[4],bL1[4];
#pragma unroll
    for(int nt=0;nt<4;nt++){ int c0=w*32+nt*8+tig*2; bL0[nt]=__ldg(b2L+c0); bL1[nt]=__ldg(b2L+c0+1); }
#pragma unroll
    for(int m=0;m<8;m++)
#pragma unroll
      for(int nt=0;nt<4;nt++){
        float d0=D[m][nt][0],d1=D[m][nt][1],d2=D[m][nt][2],d3=D[m][nt][3];
        float z0=__shfl_sync(FULLMASK,d0,tig)+bL0[nt], z1=__shfl_sync(FULLMASK,d1,tig)+bL1[nt];
        float z2=__shfl_sync(FULLMASK,d2,tig)+bL0[nt], z3=__shfl_sync(FULLMASK,d3,tig)+bL1[nt];
        int c0=w*32+nt*8+tig*2;
        float o0,o1,o2,o3;
        if (gid==0){ o0=sp_f(z0);o1=sp_f(z1);o2=sp_f(z2);o3=sp_f(z3); }
        else if (gid<7){ o0=sg_f(z0)*d0;o1=sg_f(z1)*d1;o2=sg_f(z2)*d2;o3=sg_f(z3)*d3; }
        else { o0=0.f;o1=0.f;o2=0.f;o3=0.f; }
        *(float2*)&sm[S_H+swz(m*16+gid,c0)]  =make_float2(rna(o0),rna(o1));
        *(float2*)&sm[S_H+swz(m*16+8+gid,c0)]=make_float2(rna(o2),rna(o3));
      }
  }
  __syncthreads();

  // ---------- P3: L layer3 (w0-2) | V backward (w3) ----------
  if (w<3){
    float D[8][4]={};
#pragma unroll 4
    for(int kt=0;kt<16;kt++){
      int n=8*w+gid;
      unsigned b0=F2U(g_W3L24[n*128+kt*8+tig]), b1=F2U(g_W3L24[n*128+kt*8+tig+4]);
#pragma unroll
      for(int m=0;m<8;m++){
        int r0=m*16+gid, c0=kt*8+tig;
        unsigned a0=F2U(sm[S_H+swz(r0,c0)]),   a1=F2U(sm[S_H+swz(r0+8,c0)]);
        unsigned a2=F2U(sm[S_H+swz(r0,c0+4)]), a3=F2U(sm[S_H+swz(r0+8,c0+4)]);
        mma8(D[m][0],D[m][1],D[m][2],D[m][3],a0,a1,a2,a3,b0,b1);
      }
    }
    int c0=8*w+tig*2;
    float bb0=(c0<21)?__ldg(b3L+c0):0.f, bb1=(c0+1<21)?__ldg(b3L+c0+1):0.f;
#pragma unroll
    for(int m=0;m<8;m++){
      float d0=D[m][0],d1=D[m][1],d2=D[m][2],d3=D[m][3];
      float z0=__shfl_sync(FULLMASK,d0,tig)+bb0, z1=__shfl_sync(FULLMASK,d1,tig)+bb1;
      float z2=__shfl_sync(FULLMASK,d2,tig)+bb0, z3=__shfl_sync(FULLMASK,d3,tig)+bb1;
      float o0,o1,o2,o3;
      if (gid==0){ o0=sp_f(z0);o1=sp_f(z1);o2=sp_f(z2);o3=sp_f(z3); }
      else if (gid<7){ o0=sg_f(z0)*d0;o1=sg_f(z1)*d1;o2=sg_f(z2)*d2;o3=sg_f(z3)*d3; }
      else { o0=0.f;o1=0.f;o2=0.f;o3=0.f; }
      sm[S_SL+(2*m)*200+gid*25+c0]=o0;   sm[S_SL+(2*m)*200+gid*25+c0+1]=o1;
      sm[S_SL+(2*m+1)*200+gid*25+c0]=o2; sm[S_SL+(2*m+1)*200+gid*25+c0+1]=o3;
    }
  } else {
    float D[16][4]={};
#pragma unroll 2
    for(int kt=0;kt<16;kt++){
      int c0=kt*8+tig;
      unsigned a0=F2U(sm[S_R2+swz(gid,c0)]),   a1=F2U(sm[S_R2+swz(gid+8,c0)]);
      unsigned a2=F2U(sm[S_R2+swz(gid,c0+4)]), a3=F2U(sm[S_R2+swz(gid+8,c0+4)]);
#pragma unroll
      for(int nt=0;nt<16;nt++){
        int n=nt*8+gid;
        mma8(D[nt][0],D[nt][1],D[nt][2],D[nt][3],a0,a1,a2,a3,
             F2U(g_W2VT[n*128+kt*8+tig]),F2U(g_W2VT[n*128+kt*8+tig+4]));
      }
    }
#pragma unroll
    for(int nt=0;nt<16;nt++){
      int c0=nt*8+tig*2;
      float2 hA=*(float2*)&sm[S_H1V+swz(gid,c0)];
      float2 hB=*(float2*)&sm[S_H1V+swz(gid+8,c0)];
      float r0=D[nt][0]*(1.f-__expf(-hA.x)), r1=D[nt][1]*(1.f-__expf(-hA.y));
      float r2=D[nt][2]*(1.f-__expf(-hB.x)), r3=D[nt][3]*(1.f-__expf(-hB.y));
      *(float2*)&sm[S_H1V+swz(gid,c0)]  =make_float2(rna(r0),rna(r1));
      *(float2*)&sm[S_H1V+swz(gid+8,c0)]=make_float2(rna(r2),rna(r3));
    }
  }
  __syncthreads();

  // ---------- P4: grad = r1 @ W1V (warp 0) ----------
  if (w==0){
    float D[2][4]={};
#pragma unroll 4
    for(int kt=0;kt<16;kt++){
      int c0=kt*8+tig;
      unsigned a0=F2U(sm[S_H1V+swz(gid,c0)]),   a1=F2U(sm[S_H1V+swz(gid+8,c0)]);
      unsigned a2=F2U(sm[S_H1V+swz(gid,c0+4)]), a3=F2U(sm[S_H1V+swz(gid+8,c0+4)]);
#pragma unroll
      for(int nt=0;nt<2;nt++){
        int n=nt*8+gid;
        mma8(D[nt][0],D[nt][1],D[nt][2],D[nt][3],a0,a1,a2,a3,
             F2U(g_W1VT16[n*128+kt*8+tig]),F2U(g_W1VT16[n*128+kt*8+tig+4]));
      }
    }
#pragma unroll
    for(int nt=0;nt<2;nt++){
      int c=nt*8+tig*2;
      if (c<12){ sm[S_SG+gid*12+c]=D[nt][0]; sm[S_SG+(gid+8)*12+c]=D[nt][2]; }
      if (c+1<12){ sm[S_SG+gid*12+c+1]=D[nt][1]; sm[S_SG+(gid+8)*12+c+1]=D[nt][3]; }
    }
  }
  __syncthreads();

  // ---------- P5: assembly + Cholesky solve (8 lanes/element) ----------
  {
    int gl=lane&7, grp=lane>>3, eloc=w*4+grp;
    int e=eb+eloc; bool valid=(e<B); if(!valid) e=B-1;
    const float* SLe=sm+S_SL+eloc*200;
    float* SDel=sm+S_H0+eloc*24;     // reuse H0 region
    float qd6[6];
#pragma unroll
    for(int j=0;j<6;j++) qd6[j]=g_qds[S][e*6+j];
    if (gl<7){
#pragma unroll
      for(int t=0;t<3;t++){
        int m=gl*3+t;
        if (m<21){
          float s=0.f;
#pragma unroll
          for(int p=0;p<6;p++) s+=qd6[p]*SLe[(1+p)*25+m];
          SDel[m]=s;
        }
      }
    }
    __syncwarp();
    int li=(gl<6)?gl:5;
    float w6[6],u6[6],Dq[6];
#pragma unroll
    for(int k=0;k<6;k++){
      float sw=0.f,su=0.f,sd=0.f;
#pragma unroll
      for(int i2=0;i2<6;i2++) if (i2>=k){
        int m=TRI(i2,k); float a=qd6[i2];
        sw+=SLe[m]*a; su+=SLe[(1+li)*25+m]*a; sd+=SDel[m]*a;
      }
      w6[k]=sw; u6[k]=su; Dq[k]=sd;
    }
    float term2=0.f;
#pragma unroll
    for(int k=0;k<6;k++) term2+=w6[k]*u6[k];
    int base=li*(li+1)/2;
    float Dw=0.f,LDq=0.f;
#pragma unroll
    for(int j2=0;j2<6;j2++) if (j2<=li){ Dw+=SDel[base+j2]*w6[j2]; LDq+=SLe[base+j2]*Dq[j2]; }
    float ci=Dw+LDq-term2;
    float qsi=g_qs[S][e*6+li];
    float gi=-sm[S_SG+eloc*12+2*li]*sinf(qsi)+sm[S_SG+eloc*12+2*li+1]*cosf(qsi);
    float lo=c_LOWER[li]+0.1f, up=c_UPPER[li]-0.1f;
    float fi;
    if ((vm>>li)&1) fi=(qsi<=lo)?c_EFFORT[li]:((qsi>=up)?-c_EFFORT[li]:0.f);
    else            fi=-5.f*(1.f/(qsi-lo)-1.f/(up-qsi));
    float tau=__ldg(action+e*6+li)*c_EFFORT[li];
    float rhs=tau-ci-gi-fi;
    int gb=lane&~7;
    float accf=rhs, yvv=0.f;
#pragma unroll
    for(int j2=0;j2<6;j2++){
      float yj=__shfl_sync(FULLMASK,accf,gb+j2)/SLe[TRI(j2,j2)];
      if (gl==j2) yvv=yj;
      if (gl>j2 && gl<6) accf-=SLe[base+j2]*yj;
    }
    float acc2=yvv, xi=0.f;
#pragma unroll
    for(int j2=5;j2>=0;j2--){
      float xj=__shfl_sync(FULLMASK,acc2,gb+j2)/SLe[TRI(j2,j2)];
      if (gl==j2) xi=xj;
      if (gl<j2) acc2-=SLe[TRI(j2,gl)]*xj;
    }
    if (gl<6 && valid) g_kqd[S][e*6+gl]=xi;
  }
}

__global__ void final_kernel(const float* __restrict__ obs, float* __restrict__ out, int B){
  int idx=blockIdx.x*blockDim.x+threadIdx.x;
  if (idx>=B*6) return;
  int i=idx/6, j=idx-i*6;
  float q0=obs[i*12+j], qd0=obs[i*12+6+j];
  const float c1=DT/6.f;
  float qn=q0+c1*(g_qds[0][idx]+2.f*g_qds[1][idx]+2.f*g_qds[2][idx]+g_qds[3][idx]);
  qn=fminf(fmaxf(qn,c_LOWER[j]),c_UPPER[j]);
  float qdn=qd0+c1*(g_kqd[0][idx]+2.f*g_kqd[1][idx]+2.f*g_kqd[2][idx]+g_kqd[3][idx]);
  out[i*12+j]=qn;
  out[i*12+6+j]=qdn;
}

extern "C" void kernel_launch(void* const* d_in, const int* in_sizes, int n_in,
                              void* d_out, int out_size)
{
  const float* obs   =(const float*)d_in[0];
  const float* action=(const float*)d_in[1];
  const float* W1L=(const float*)d_in[2];  const float* b1L=(const float*)d_in[3];
  const float* W2L=(const float*)d_in[4];  const float* b2L=(const float*)d_in[5];
  const float* W3L=(const float*)d_in[6];  const float* b3L=(const float*)d_in[7];
  const float* W1V=(const float*)d_in[8];  const float* b1V=(const float*)d_in[9];
  const float* W2V=(const float*)d_in[10]; const float* b2V=(const float*)d_in[11];
  const float* W3V=(const float*)d_in[12]; const float* b3V=(const float*)d_in[13];
  (void)b3V;
  float* out=(float*)d_out;
  int B=in_sizes[0]/12;
  if (B>MAXB) B=MAXB;

  static int attr_set=0;
  if (!attr_set){
    cudaFuncSetAttribute(accel_mma_kernel, cudaFuncAttributeMaxDynamicSharedMemorySize, SMEM_FLOATS*4);
    attr_set=1;
  }

  int nbE=(B*6+127)/128;
  int nbA=(B+15)/16;

  zero_viol_kernel<<<1,32>>>();
  prep_weights_kernel<<<229,256>>>(W1L,b1L,W2L,W3L,W1V,b1V,W2V);
  for (int s=0;s<4;s++){
    prep_kernel<<<nbE,128>>>(s,obs,B);
    accel_mma_kernel<<<nbA,128,SMEM_FLOATS*4>>>(s,action,b2L,b3L,b2V,W3V,B);
  }
  final_kernel<<<nbE,128>>>(obs,out,B);
}

// round 5
// speedup vs baseline: 4.9603x; 2.6765x over previous
#include <cuda_runtime.h>
#include <math.h>

#define MAXB 16384
#define DT 0.01f
#define FULLMASK 0xffffffffu
#define TRI(i,j) ((i)*((i)+1)/2+(j))

__constant__ float c_LOWER[6] = {-6.28f,-6.28f,-3.14f,-6.28f,-6.28f,-6.28f};
__constant__ float c_UPPER[6] = { 6.28f, 6.28f, 3.14f, 6.28f, 6.28f, 6.28f};
__constant__ float c_EFFORT[6]= {150.f,150.f,150.f,28.f,28.f,28.f};

__device__ float g_qs [4][MAXB*6];
__device__ float g_qds[4][MAXB*6];
__device__ float g_kqd[4][MAXB*6];
__device__ int   g_viol[4];

// tf32-prepped weights, pair-packed for B fragments: idx ((n*KT+kt)*4+tig) -> {W[n][kt*8+tig], W[n][kt*8+tig+4]}
__device__ float2 g_W1L16 [128*2*4];
__device__ float2 g_W2Lp  [128*16*4];
__device__ float2 g_W3L24 [24*16*4];
__device__ float2 g_W1V16 [128*2*4];
__device__ float2 g_W2Vp  [128*16*4];
__device__ float2 g_W2VT  [128*16*4];
__device__ float2 g_W1VT16[16*16*4];

__device__ __forceinline__ float rna(float x){
  unsigned u; asm("cvt.rna.tf32.f32 %0, %1;":"=r"(u):"f"(x)); return __uint_as_float(u);
}
__device__ __forceinline__ float sp_f(float x){ return fmaxf(x,0.f)+__logf(1.f+__expf(-fabsf(x))); }
__device__ __forceinline__ float sg_f(float x){ return __fdividef(1.f,1.f+__expf(-x)); }
__device__ __forceinline__ void mma8(float&d0,float&d1,float&d2,float&d3,
    unsigned a0,unsigned a1,unsigned a2,unsigned a3,unsigned b0,unsigned b1){
  asm volatile("mma.sync.aligned.m16n8k8.row.col.f32.tf32.tf32.f32 "
    "{%0,%1,%2,%3},{%4,%5,%6,%7},{%8,%9},{%0,%1,%2,%3};"
    :"+f"(d0),"+f"(d1),"+f"(d2),"+f"(d3)
    :"r"(a0),"r"(a1),"r"(a2),"r"(a3),"r"(b0),"r"(b1));
}
__device__ __forceinline__ void ldsm4(unsigned&r0,unsigned&r1,unsigned&r2,unsigned&r3,unsigned a){
  asm volatile("ldmatrix.sync.aligned.m8n8.x4.shared.b16 {%0,%1,%2,%3},[%4];"
    :"=r"(r0),"=r"(r1),"=r"(r2),"=r"(r3):"r"(a));
}
__device__ __forceinline__ int swz(int r,int c){ return (r<<7)+(c^((r&7)<<2)); }
#define F2U __float_as_uint

__global__ void zero_viol_kernel(){ if (threadIdx.x<4) g_viol[threadIdx.x]=0; }

__global__ void prep_weights_kernel(const float* __restrict__ W1L,const float* __restrict__ b1L,
    const float* __restrict__ W2L,const float* __restrict__ W3L,
    const float* __restrict__ W1V,const float* __restrict__ b1V,const float* __restrict__ W2V){
  int i=blockIdx.x*blockDim.x+threadIdx.x;
  if (i<1024){
    int n=i>>3, kt=(i>>2)&1, tig=i&3; int k0=kt*8+tig, k1=k0+4;
    float v0=k0<12?W1L[n*12+k0]:(k0==12?b1L[n]:0.f);
    float v1=k1<12?W1L[n*12+k1]:(k1==12?b1L[n]:0.f);
    g_W1L16[i]=make_float2(rna(v0),rna(v1));
  } else if (i<9216){ int j=i-1024; int n=j>>6,kt=(j>>2)&15,tig=j&3; int k0=kt*8+tig;
    g_W2Lp[j]=make_float2(rna(W2L[n*128+k0]),rna(W2L[n*128+k0+4]));
  } else if (i<10752){ int j=i-9216; int n=j>>6,kt=(j>>2)&15,tig=j&3; int k0=kt*8+tig;
    g_W3L24[j]=make_float2(rna(n<21?W3L[n*128+k0]:0.f),rna(n<21?W3L[n*128+k0+4]:0.f));
  } else if (i<11776){ int j=i-10752; int n=j>>3,kt=(j>>2)&1,tig=j&3; int k0=kt*8+tig,k1=k0+4;
    float v0=k0<12?W1V[n*12+k0]:(k0==12?b1V[n]:0.f);
    float v1=k1<12?W1V[n*12+k1]:(k1==12?b1V[n]:0.f);
    g_W1V16[j]=make_float2(rna(v0),rna(v1));
  } else if (i<19968){ int j=i-11776; int n=j>>6,kt=(j>>2)&15,tig=j&3; int k0=kt*8+tig;
    g_W2Vp[j]=make_float2(rna(W2V[n*128+k0]),rna(W2V[n*128+k0+4]));
  } else if (i<28160){ int j=i-19968; int n=j>>6,kt=(j>>2)&15,tig=j&3; int k0=kt*8+tig;
    g_W2VT[j]=make_float2(rna(W2V[k0*128+n]),rna(W2V[(k0+4)*128+n]));
  } else if (i<29184){ int j=i-28160; int n=j>>6,kt=(j>>2)&15,tig=j&3; int k0=kt*8+tig;
    g_W1VT16[j]=make_float2(rna(n<12?W1V[k0*12+n]:0.f),rna(n<12?W1V[(k0+4)*12+n]:0.f));
  }
}

__global__ void prep_kernel(int S, const float* __restrict__ obs, int B){
  int idx=blockIdx.x*blockDim.x+threadIdx.x;
  if (idx>=B*6) return;
  int i=idx/6, j=idx-i*6;
  float q0=obs[i*12+j], qd0=obs[i*12+6+j];
  float qs,qds;
  if      (S==0){ qs=q0;                       qds=qd0; }
  else if (S==1){ qs=q0+0.5f*DT*qd0;           qds=qd0+0.5f*DT*g_kqd[0][idx]; }
  else if (S==2){ qs=q0+0.5f*DT*g_qds[1][idx]; qds=qd0+0.5f*DT*g_kqd[1][idx]; }
  else          { qs=q0+DT*g_qds[2][idx];      qds=qd0+DT*g_kqd[2][idx]; }
  g_qs[S][idx]=qs; g_qds[S][idx]=qds;
  float lo=c_LOWER[j]+0.1f, up=c_UPPER[j]-0.1f;
  if (qs<=lo || qs>=up) atomicOr(&g_viol[S], 1<<j);
}

// smem layout (floats)
#define S_H    0
#define S_H0   16384
#define S_VIN  18944
#define S_H1V  19264
#define S_R2   21312
#define S_SL   23360
#define S_SG   26560
#define SMEM_FLOATS 26752

__global__ void __launch_bounds__(256,2)
accel_mma_kernel(int S, const float* __restrict__ action,
    const float* __restrict__ b2L, const float* __restrict__ b3L,
    const float* __restrict__ b2V, const float* __restrict__ W3V, int B)
{
  extern __shared__ float sm[];
  const int tid=threadIdx.x, w=tid>>5, lane=tid&31;
  const int gid=lane>>2, tig=lane&3;
  const int eb=blockIdx.x*16;
  const int vm=g_viol[S];
  const unsigned smb=(unsigned)__cvta_generic_to_shared(sm);

  // per-lane ldmatrix address components
  const int sub=lane>>3, l7=lane&7;
  const int lm_row = l7 + ((sub&1)<<3);
  const unsigned lm_koff = (unsigned)(l7>>1);
  const unsigned lm_cfix4 = (unsigned)(((sub&2)<<3) ^ ((l7&1)<<4));
  const unsigned base_H   = smb + S_H*4   + lm_row*512 + lm_cfix4;
  const unsigned base_H1V = smb + S_H1V*4 + lm_row*512 + lm_cfix4;
  const unsigned base_R2  = smb + S_R2*4  + lm_row*512 + lm_cfix4;
  const unsigned base_H0  = smb + S_H0*4  + lm_row*80 + ((sub&2)<<3);
  const unsigned base_VIN = smb + S_VIN*4 + lm_row*80 + ((sub&2)<<3);

  // ---------- P0: build A matrices ----------
  if (tid<128){
    int row=tid, ch=row&7, el=row>>3;
    int e=eb+el; if (e>=B) e=B-1;
    float t16[16];
#pragma unroll
    for(int k=0;k<16;k++) t16[k]=0.f;
    if (ch==0){
#pragma unroll
      for(int j=0;j<6;j++){ float qj=g_qs[S][e*6+j]; t16[2*j]=cosf(qj); t16[2*j+1]=sinf(qj); }
      t16[12]=1.f;
    } else if (ch<7){
      int p=ch-1; float qp=g_qs[S][e*6+p];
      t16[2*p]=-sinf(qp); t16[2*p+1]=cosf(qp);
    }
#pragma unroll
    for(int k=0;k<16;k++) sm[S_H0+row*20+k]=rna(t16[k]);
    if (ch==0){
#pragma unroll
      for(int k=0;k<16;k++) sm[S_VIN+el*20+k]=rna(t16[k]);
    }
  }
  __syncthreads();

  // ---------- P1: V layer1 + L layer1 (K=16) ----------
  {
    float DV[2][4]={};
#pragma unroll
    for(int kt=0;kt<2;kt++){
      unsigned a0,a1,a2,a3; ldsm4(a0,a1,a2,a3, base_VIN + kt*32);
#pragma unroll
      for(int nt=0;nt<2;nt++){
        int n=w*16+nt*8+gid;
        float2 bf=g_W1V16[(n*2+kt)*4+tig];
        mma8(DV[nt][0],DV[nt][1],DV[nt][2],DV[nt][3],a0,a1,a2,a3,F2U(bf.x),F2U(bf.y));
      }
    }
#pragma unroll
    for(int nt=0;nt<2;nt++){
      int c0=w*16+nt*8+tig*2;
      *(float2*)&sm[S_H1V+swz(gid,c0)]  =make_float2(rna(sp_f(DV[nt][0])),rna(sp_f(DV[nt][1])));
      *(float2*)&sm[S_H1V+swz(gid+8,c0)]=make_float2(rna(sp_f(DV[nt][2])),rna(sp_f(DV[nt][3])));
    }
    float D[8][2][4]={};
#pragma unroll
    for(int kt=0;kt<2;kt++){
      float2 bf[2];
#pragma unroll
      for(int nt=0;nt<2;nt++){ int n=w*16+nt*8+gid; bf[nt]=g_W1L16[(n*2+kt)*4+tig]; }
#pragma unroll
      for(int m=0;m<8;m++){
        unsigned a0,a1,a2,a3; ldsm4(a0,a1,a2,a3, base_H0 + m*1280 + kt*32);
#pragma unroll
        for(int nt=0;nt<2;nt++)
          mma8(D[m][nt][0],D[m][nt][1],D[m][nt][2],D[m][nt][3],a0,a1,a2,a3,F2U(bf[nt].x),F2U(bf[nt].y));
      }
    }
#pragma unroll
    for(int m=0;m<8;m++)
#pragma unroll
      for(int nt=0;nt<2;nt++){
        float d0=D[m][nt][0],d1=D[m][nt][1],d2=D[m][nt][2],d3=D[m][nt][3];
        float z0=__shfl_sync(FULLMASK,d0,tig), z1=__shfl_sync(FULLMASK,d1,tig);
        float z2=__shfl_sync(FULLMASK,d2,tig), z3=__shfl_sync(FULLMASK,d3,tig);
        int c0=w*16+nt*8+tig*2;
        float o0,o1,o2,o3;
        if (gid==0){ o0=sp_f(z0);o1=sp_f(z1);o2=sp_f(z2);o3=sp_f(z3); }
        else if (gid<7){ o0=sg_f(z0)*d0;o1=sg_f(z1)*d1;o2=sg_f(z2)*d2;o3=sg_f(z3)*d3; }
        else { o0=0.f;o1=0.f;o2=0.f;o3=0.f; }
        *(float2*)&sm[S_H+swz(m*16+gid,c0)]  =make_float2(rna(o0),rna(o1));
        *(float2*)&sm[S_H+swz(m*16+8+gid,c0)]=make_float2(rna(o2),rna(o3));
      }
  }
  __syncthreads();

  // ---------- P2: V layer2 + L layer2 (in place) ----------
  {
    float DV[2][4]={};
#pragma unroll 4
    for(int kt=0;kt<16;kt++){
      unsigned a0,a1,a2,a3; ldsm4(a0,a1,a2,a3, base_H1V + (((unsigned)kt^lm_koff)<<5));
#pragma unroll
      for(int nt=0;nt<2;nt++){
        int n=w*16+nt*8+gid;
        float2 bf=g_W2Vp[(n*16+kt)*4+tig];
        mma8(DV[nt][0],DV[nt][1],DV[nt][2],DV[nt][3],a0,a1,a2,a3,F2U(bf.x),F2U(bf.y));
      }
    }
#pragma unroll
    for(int nt=0;nt<2;nt++){
      int c0=w*16+nt*8+tig*2;
      float bv0=__ldg(b2V+c0),bv1=__ldg(b2V+c0+1),w30=__ldg(W3V+c0),w31=__ldg(W3V+c0+1);
      *(float2*)&sm[S_R2+swz(gid,c0)]  =make_float2(rna(w30*sg_f(DV[nt][0]+bv0)),rna(w31*sg_f(DV[nt][1]+bv1)));
      *(float2*)&sm[S_R2+swz(gid+8,c0)]=make_float2(rna(w30*sg_f(DV[nt][2]+bv0)),rna(w31*sg_f(DV[nt][3]+bv1)));
    }
    float D[8][2][4]={};
#pragma unroll 2
    for(int kt=0;kt<16;kt++){
      float2 bf[2];
#pragma unroll
      for(int nt=0;nt<2;nt++){ int n=w*16+nt*8+gid; bf[nt]=g_W2Lp[(n*16+kt)*4+tig]; }
      unsigned koff5=(((unsigned)kt^lm_koff)<<5);
#pragma unroll
      for(int m=0;m<8;m++){
        unsigned a0,a1,a2,a3; ldsm4(a0,a1,a2,a3, base_H + m*8192 + koff5);
#pragma unroll
        for(int nt=0;nt<2;nt++)
          mma8(D[m][nt][0],D[m][nt][1],D[m][nt][2],D[m][nt][3],a0,a1,a2,a3,F2U(bf[nt].x),F2U(bf[nt].y));
      }
    }
    __syncthreads();   // all warps done reading H
    float bL0[2],bL1[2];
#pragma unroll
    for(int nt=0;nt<2;nt++){ int c0=w*16+nt*8+tig*2; bL0[nt]=__ldg(b2L+c0); bL1[nt]=__ldg(b2L+c0+1); }
#pragma unroll
    for(int m=0;m<8;m++)
#pragma unroll
      for(int nt=0;nt<2;nt++){
        float d0=D[m][nt][0],d1=D[m][nt][1],d2=D[m][nt][2],d3=D[m][nt][3];
        float z0=__shfl_sync(FULLMASK,d0,tig)+bL0[nt], z1=__shfl_sync(FULLMASK,d1,tig)+bL1[nt];
        float z2=__shfl_sync(FULLMASK,d2,tig)+bL0[nt], z3=__shfl_sync(FULLMASK,d3,tig)+bL1[nt];
        int c0=w*16+nt*8+tig*2;
        float o0,o1,o2,o3;
        if (gid==0){ o0=sp_f(z0);o1=sp_f(z1);o2=sp_f(z2);o3=sp_f(z3); }
        else if (gid<7){ o0=sg_f(z0)*d0;o1=sg_f(z1)*d1;o2=sg_f(z2)*d2;o3=sg_f(z3)*d3; }
        else { o0=0.f;o1=0.f;o2=0.f;o3=0.f; }
        *(float2*)&sm[S_H+swz(m*16+gid,c0)]  =make_float2(rna(o0),rna(o1));
        *(float2*)&sm[S_H+swz(m*16+8+gid,c0)]=make_float2(rna(o2),rna(o3));
      }
  }
  __syncthreads();

  // ---------- P3: L layer3 (w0-2) | V backward (w4-7) ----------
  if (w<3){
    float D3[8][4]={};
#pragma unroll 4
    for(int kt=0;kt<16;kt++){
      float2 bf=g_W3L24[((w*8+gid)*16+kt)*4+tig];
      unsigned koff5=(((unsigned)kt^lm_koff)<<5);
#pragma unroll
      for(int m=0;m<8;m++){
        unsigned a0,a1,a2,a3; ldsm4(a0,a1,a2,a3, base_H + m*8192 + koff5);
        mma8(D3[m][0],D3[m][1],D3[m][2],D3[m][3],a0,a1,a2,a3,F2U(bf.x),F2U(bf.y));
      }
    }
    int c0=w*8+tig*2;
    float bb0=(c0<21)?__ldg(b3L+c0):0.f, bb1=(c0+1<21)?__ldg(b3L+c0+1):0.f;
#pragma unroll
    for(int m=0;m<8;m++){
      float d0=D3[m][0],d1=D3[m][1],d2=D3[m][2],d3=D3[m][3];
      float z0=__shfl_sync(FULLMASK,d0,tig)+bb0, z1=__shfl_sync(FULLMASK,d1,tig)+bb1;
      float z2=__shfl_sync(FULLMASK,d2,tig)+bb0, z3=__shfl_sync(FULLMASK,d3,tig)+bb1;
      float o0,o1,o2,o3;
      if (gid==0){ o0=sp_f(z0);o1=sp_f(z1);o2=sp_f(z2);o3=sp_f(z3); }
      else if (gid<7){ o0=sg_f(z0)*d0;o1=sg_f(z1)*d1;o2=sg_f(z2)*d2;o3=sg_f(z3)*d3; }
      else { o0=0.f;o1=0.f;o2=0.f;o3=0.f; }
      sm[S_SL+(2*m)*200+gid*25+c0]=o0;   sm[S_SL+(2*m)*200+gid*25+c0+1]=o1;
      sm[S_SL+(2*m+1)*200+gid*25+c0]=o2; sm[S_SL+(2*m+1)*200+gid*25+c0+1]=o3;
    }
  } else if (w>=4){
    float D[4][4]={};
#pragma unroll 4
    for(int kt=0;kt<16;kt++){
      unsigned a0,a1,a2,a3; ldsm4(a0,a1,a2,a3, base_R2 + (((unsigned)kt^lm_koff)<<5));
#pragma unroll
      for(int nt=0;nt<4;nt++){
        int n=(w-4)*32+nt*8+gid;
        float2 bf=g_W2VT[(n*16+kt)*4+tig];
        mma8(D[nt][0],D[nt][1],D[nt][2],D[nt][3],a0,a1,a2,a3,F2U(bf.x),F2U(bf.y));
      }
    }
#pragma unroll
    for(int nt=0;nt<4;nt++){
      int c0=(w-4)*32+nt*8+tig*2;
      float2 hA=*(float2*)&sm[S_H1V+swz(gid,c0)];
      float2 hB=*(float2*)&sm[S_H1V+swz(gid+8,c0)];
      float r0=D[nt][0]*(1.f-__expf(-hA.x)), r1=D[nt][1]*(1.f-__expf(-hA.y));
      float r2=D[nt][2]*(1.f-__expf(-hB.x)), r3=D[nt][3]*(1.f-__expf(-hB.y));
      *(float2*)&sm[S_H1V+swz(gid,c0)]  =make_float2(rna(r0),rna(r1));
      *(float2*)&sm[S_H1V+swz(gid+8,c0)]=make_float2(rna(r2),rna(r3));
    }
  }
  __syncthreads();

  // ---------- P4: grad = r1 @ W1V (warp 0) ----------
  if (w==0){
    float D[2][4]={};
#pragma unroll 4
    for(int kt=0;kt<16;kt++){
      unsigned a0,a1,a2,a3; ldsm4(a0,a1,a2,a3, base_H1V + (((unsigned)kt^lm_koff)<<5));
#pragma unroll
      for(int nt=0;nt<2;nt++){
        int n=nt*8+gid;
        float2 bf=g_W1VT16[(n*16+kt)*4+tig];
        mma8(D[nt][0],D[nt][1],D[nt][2],D[nt][3],a0,a1,a2,a3,F2U(bf.x),F2U(bf.y));
      }
    }
#pragma unroll
    for(int nt=0;nt<2;nt++){
      int c=nt*8+tig*2;
      if (c<12){ sm[S_SG+gid*12+c]=D[nt][0]; sm[S_SG+(gid+8)*12+c]=D[nt][2]; }
      if (c+1<12){ sm[S_SG+gid*12+c+1]=D[nt][1]; sm[S_SG+(gid+8)*12+c+1]=D[nt][3]; }
    }
  }
  __syncthreads();

  // ---------- P5: assembly + Cholesky solve (warps 0-3, 8 lanes/element) ----------
  if (w<4){
    int gl=lane&7, grp=lane>>3, eloc=w*4+grp;
    int e=eb+eloc; bool valid=(e<B); if(!valid) e=B-1;
    const float* SLe=sm+S_SL+eloc*200;
    float* SDel=sm+S_H0+eloc*24;
    float qd6[6];
#pragma unroll
    for(int j=0;j<6;j++) qd6[j]=g_qds[S][e*6+j];
    if (gl<7){
#pragma unroll
      for(int t=0;t<3;t++){
        int m=gl*3+t;
        if (m<21){
          float s=0.f;
#pragma unroll
          for(int p=0;p<6;p++) s+=qd6[p]*SLe[(1+p)*25+m];
          SDel[m]=s;
        }
      }
    }
    __syncwarp();
    int li=(gl<6)?gl:5;
    float w6[6],u6[6],Dq[6];
#pragma unroll
    for(int k=0;k<6;k++){
      float sw=0.f,su=0.f,sd=0.f;
#pragma unroll
      for(int i2=0;i2<6;i2++) if (i2>=k){
        int m=TRI(i2,k); float a=qd6[i2];
        sw+=SLe[m]*a; su+=SLe[(1+li)*25+m]*a; sd+=SDel[m]*a;
      }
      w6[k]=sw; u6[k]=su; Dq[k]=sd;
    }
    float term2=0.f;
#pragma unroll
    for(int k=0;k<6;k++) term2+=w6[k]*u6[k];
    int base=li*(li+1)/2;
    float Dw=0.f,LDq=0.f;
#pragma unroll
    for(int j2=0;j2<6;j2++) if (j2<=li){ Dw+=SDel[base+j2]*w6[j2]; LDq+=SLe[base+j2]*Dq[j2]; }
    float ci=Dw+LDq-term2;
    float qsi=g_qs[S][e*6+li];
    float gi=-sm[S_SG+eloc*12+2*li]*sinf(qsi)+sm[S_SG+eloc*12+2*li+1]*cosf(qsi);
    float lo=c_LOWER[li]+0.1f, up=c_UPPER[li]-0.1f;
    float fi;
    if ((vm>>li)&1) fi=(qsi<=lo)?c_EFFORT[li]:((qsi>=up)?-c_EFFORT[li]:0.f);
    else            fi=-5.f*(1.f/(qsi-lo)-1.f/(up-qsi));
    float tau=__ldg(action+e*6+li)*c_EFFORT[li];
    float rhs=tau-ci-gi-fi;
    int gb=lane&~7;
    float accf=rhs, yvv=0.f;
#pragma unroll
    for(int j2=0;j2<6;j2++){
      float yj=__shfl_sync(FULLMASK,accf,gb+j2)/SLe[TRI(j2,j2)];
      if (gl==j2) yvv=yj;
      if (gl>j2 && gl<6) accf-=SLe[base+j2]*yj;
    }
    float acc2=yvv, xi=0.f;
#pragma unroll
    for(int j2=5;j2>=0;j2--){
      float xj=__shfl_sync(FULLMASK,acc2,gb+j2)/SLe[TRI(j2,j2)];
      if (gl==j2) xi=xj;
      if (gl<j2) acc2-=SLe[TRI(j2,gl)]*xj;
    }
    if (gl<6 && valid) g_kqd[S][e*6+gl]=xi;
  }
}

__global__ void final_kernel(const float* __restrict__ obs, float* __restrict__ out, int B){
  int idx=blockIdx.x*blockDim.x+threadIdx.x;
  if (idx>=B*6) return;
  int i=idx/6, j=idx-i*6;
  float q0=obs[i*12+j], qd0=obs[i*12+6+j];
  const float c1=DT/6.f;
  float qn=q0+c1*(g_qds[0][idx]+2.f*g_qds[1][idx]+2.f*g_qds[2][idx]+g_qds[3][idx]);
  qn=fminf(fmaxf(qn,c_LOWER[j]),c_UPPER[j]);
  float qdn=qd0+c1*(g_kqd[0][idx]+2.f*g_kqd[1][idx]+2.f*g_kqd[2][idx]+g_kqd[3][idx]);
  out[i*12+j]=qn;
  out[i*12+6+j]=qdn;
}

extern "C" void kernel_launch(void* const* d_in, const int* in_sizes, int n_in,
                              void* d_out, int out_size)
{
  const float* obs   =(const float*)d_in[0];
  const float* action=(const float*)d_in[1];
  const float* W1L=(const float*)d_in[2];  const float* b1L=(const float*)d_in[3];
  const float* W2L=(const float*)d_in[4];  const float* b2L=(const float*)d_in[5];
  const float* W3L=(const float*)d_in[6];  const float* b3L=(const float*)d_in[7];
  const float* W1V=(const float*)d_in[8];  const float* b1V=(const float*)d_in[9];
  const float* W2V=(const float*)d_in[10]; const float* b2V=(const float*)d_in[11];
  const float* W3V=(const float*)d_in[12]; const float* b3V=(const float*)d_in[13];
  (void)b3V;
  float* out=(float*)d_out;
  int B=in_sizes[0]/12;
  if (B>MAXB) B=MAXB;

  cudaFuncSetAttribute(accel_mma_kernel, cudaFuncAttributeMaxDynamicSharedMemorySize, SMEM_FLOATS*4);

  int nbE=(B*6+127)/128;
  int nbA=(B+15)/16;

  zero_viol_kernel<<<1,32>>>();
  prep_weights_kernel<<<114,256>>>(W1L,b1L,W2L,W3L,W1V,b1V,W2V);
  for (int s=0;s<4;s++){
    prep_kernel<<<nbE,128>>>(s,obs,B);
    accel_mma_kernel<<<nbA,256,SMEM_FLOATS*4>>>(s,action,b2L,b3L,b2V,W3V,B);
  }
  final_kernel<<<nbE,128>>>(obs,out,B);
}